// round 14
// baseline (speedup 1.0000x reference)
#include <cuda_runtime.h>
#include <cuda_bf16.h>
#include <math.h>

// ---------------- problem constants ----------------
#define BB   128
#define TT   64
#define NIMG (BB*TT)          // 8192
#define HI   50
#define WI   60
#define HO   25
#define WO   30
#define EMB  750
#define QS   100
#define HSZ  400
#define NCLS 10
#define KSPLIT 2
#define PIMG_SZ (52 * 64 + 16)     // 3344 floats per padded image

// conv dynamic SMEM layout (bytes)
#define CONV_PIMG_OFF  0
#define CONV_CARRY_OFF (2 * PIMG_SZ * 4)                    // 26752
#define CONV_EMB_OFF   (CONV_CARRY_OFF + 8 * 16 * 32 * 8)   // +32768 = 59520
#define CONV_W_OFF     (CONV_EMB_OFF + 2 * EMB * 4)         // +6000  = 65520
#define CONV_SMEM      (CONV_W_OFF + (72 + 72 + 8) * 8)     // +1216  = 66736

// ---------------- f32x2 packed helpers ----------------
typedef unsigned long long f32x2;

__device__ __forceinline__ f32x2 pk2(float x, float y) {
    f32x2 r; asm("mov.b64 %0, {%1, %2};" : "=l"(r) : "f"(x), "f"(y)); return r;
}
__device__ __forceinline__ void unpk2(f32x2 v, float &x, float &y) {
    asm("mov.b64 {%0, %1}, %2;" : "=f"(x), "=f"(y) : "l"(v));
}
__device__ __forceinline__ void fma2(f32x2 &d, f32x2 a, f32x2 b) {
    asm("fma.rn.f32x2 %0, %1, %2, %0;" : "+l"(d) : "l"(a), "l"(b));
}
__device__ __forceinline__ f32x2 mul2(f32x2 a, f32x2 b) {
    f32x2 d; asm("mul.rn.f32x2 %0, %1, %2;" : "=l"(d) : "l"(a), "l"(b)); return d;
}
__device__ __forceinline__ f32x2 add2(f32x2 a, f32x2 b) {
    f32x2 d; asm("add.rn.f32x2 %0, %1, %2;" : "=l"(d) : "l"(a), "l"(b)); return d;
}
__device__ __forceinline__ float lky(float x) { return fmaxf(x, 0.01f * x); }
// packed leaky: 0.505*x + 0.495*|x|
__device__ __forceinline__ f32x2 lky2(f32x2 x) {
    f32x2 a = x & 0x7FFFFFFF7FFFFFFFULL;
    f32x2 r = mul2(x, pk2(0.505f, 0.505f));
    fma2(r, a, pk2(0.495f, 0.495f));
    return r;
}

// ---------------- scratch (static device memory; allowed) ----------------
__device__ float g_emb[NIMG * EMB];               // 24.6 MB
__device__ float g_E[KSPLIT * NIMG * QS];         //  6.6 MB (K-split partials)
__device__ float g_Hall[NIMG * HSZ];              // 13.1 MB
__device__ float g_OutAll[KSPLIT * NIMG * QS];    //  6.6 MB (K-split partials)

// ---------------- no-op kernel: keep ncu capture on recurrence ----------------
__global__ void nop_kernel_a() {}

// =====================================================================
// Conv v7 (unchanged from R12): strip + SMEM carry, 2 images per CTA.
// =====================================================================
__global__ void __launch_bounds__(256, 3) conv_embed_kernel(
    const float *__restrict__ In,
    const float *__restrict__ w1, const float *__restrict__ b1,
    const float *__restrict__ w2, const float *__restrict__ b2,
    float *__restrict__ emb_out)
{
    extern __shared__ char smraw[];
    float *pimg  = (float *)(smraw + CONV_PIMG_OFF);   // [2][PIMG_SZ]
    f32x2 *carry = (f32x2 *)(smraw + CONV_CARRY_OFF);  // [8][16][32]
    float *emb_s = (float *)(smraw + CONV_EMB_OFF);    // [2][EMB]
    f32x2 *sw1   = (f32x2 *)(smraw + CONV_W_OFF);      // [9*8]
    f32x2 *sw2   = sw1 + 72;                            // [9*8]
    f32x2 *sb1   = sw2 + 72;                            // [8]

    const int tid = threadIdx.x;
    const int wid = tid >> 5;
    const int lane = tid & 31;
    const int cp = lane & 7;
    const int xq = lane >> 3;
    const float *imgg0 = In + (size_t)(2 * blockIdx.x) * (HI * WI);

    for (int i = tid; i < 2 * PIMG_SZ; i += 256) {
        int im = (i >= PIMG_SZ) ? 1 : 0;
        int idx = i - im * PIMG_SZ;
        int pr = idx >> 6, pc = idx & 63;
        int r = pr - 1, x = pc - 1;
        float v = (idx < 52 * 64 && r >= 0 && r < HI && x >= 0 && x < WI)
                  ? imgg0[(size_t)im * (HI * WI) + r * WI + x] : 0.f;
        pimg[im * PIMG_SZ + idx] = v;
    }
    if (tid < 72) {
        int tap = tid / 8, c = tid % 8;
        sw1[tid] = pk2(w1[(2 * c) * 9 + tap], w1[(2 * c + 1) * 9 + tap]);
        sw2[tid] = pk2(w2[(2 * c) * 9 + tap], w2[(2 * c + 1) * 9 + tap]);
    }
    if (tid < 8) sb1[tid] = pk2(b1[2 * tid], b1[2 * tid + 1]);
    const float bias2 = b2[0];
    __syncthreads();

    f32x2 rw1[9];
    #pragma unroll
    for (int t = 0; t < 9; t++) rw1[t] = sw1[t * 8 + cp];
    const f32x2 rb1 = sb1[cp];

    const int n_out = (xq == 3) ? 6 : 8;
    const int pxb = 16 * xq;

    const int im = wid >> 2;
    const int wl = wid & 3;
    const int s0 = (wl == 0) ? 0 : (7 + 6 * (wl - 1));
    const int len = (wl == 0) ? 7 : 6;
    const float *P = pimg + im * PIMG_SZ;
    f32x2 *cw = carry + wid * (16 * 32);

    #pragma unroll 1
    for (int ii = 0; ii < len; ii++) {
        const int i2 = s0 + ii;
        f32x2 acc[8];
        #pragma unroll
        for (int o = 0; o < 8; o++) acc[o] = 0ull;

        #pragma unroll 1
        for (int dy2 = 0; dy2 < 3; dy2++) {
            const int r = 2 * i2 - 1 + dy2;
            const bool restore = (dy2 == 0) && (ii > 0);
            const bool have = restore || (r >= 0);
            const bool saving = (dy2 == 2) && (ii + 1 < len);
            f32x2 w2a = sw2[(dy2 * 3 + 0) * 8 + cp];
            f32x2 w2b = sw2[(dy2 * 3 + 1) * 8 + cp];
            f32x2 w2c = sw2[(dy2 * 3 + 2) * 8 + cp];
            f32x2 vtop = 0ull;

            if (have) {
                f32x2 vc[8];
                if (restore) {
                    #pragma unroll
                    for (int j = 0; j < 8; j++) vc[j] = cw[(8 + j) * 32 + lane];
                } else {
                    #pragma unroll
                    for (int j = 0; j < 8; j++) vc[j] = rb1;
                    #pragma unroll
                    for (int dy = 0; dy < 3; dy++) {
                        const float *rowp = &P[(r + dy) * 64 + pxb + 8];
                        float4 q0 = *(const float4 *)(rowp + 0);
                        float4 q1 = *(const float4 *)(rowp + 4);
                        float2 q2 = *(const float2 *)(rowp + 8);
                        float f[10] = {q0.x,q0.y,q0.z,q0.w, q1.x,q1.y,q1.z,q1.w,
                                       q2.x,q2.y};
                        f32x2 wa = rw1[dy*3+0], wb = rw1[dy*3+1], wc = rw1[dy*3+2];
                        #pragma unroll
                        for (int j = 0; j < 8; j++) {
                            fma2(vc[j], pk2(f[j+0], f[j+0]), wa);
                            fma2(vc[j], pk2(f[j+1], f[j+1]), wb);
                            fma2(vc[j], pk2(f[j+2], f[j+2]), wc);
                        }
                    }
                    #pragma unroll
                    for (int j = 0; j < 8; j++) vc[j] = lky2(vc[j]);
                }
                if (saving) {
                    #pragma unroll
                    for (int j = 0; j < 8; j++) cw[(8 + j) * 32 + lane] = vc[j];
                }
                fma2(acc[4], vc[0], w2b); fma2(acc[4], vc[1], w2c);
                fma2(acc[5], vc[1], w2a); fma2(acc[5], vc[2], w2b); fma2(acc[5], vc[3], w2c);
                fma2(acc[6], vc[3], w2a); fma2(acc[6], vc[4], w2b); fma2(acc[6], vc[5], w2c);
                fma2(acc[7], vc[5], w2a); fma2(acc[7], vc[6], w2b); fma2(acc[7], vc[7], w2c);
                vtop = vc[7];
            }

            f32x2 vm1 = __shfl_up_sync(0xffffffffu, vtop, 8);
            if (xq == 0) vm1 = 0ull;

            if (have) {
                f32x2 vd[8];
                if (restore) {
                    #pragma unroll
                    for (int j = 0; j < 8; j++) vd[j] = cw[j * 32 + lane];
                } else {
                    #pragma unroll
                    for (int j = 0; j < 8; j++) vd[j] = rb1;
                    #pragma unroll
                    for (int dy = 0; dy < 3; dy++) {
                        const float *rowp = &P[(r + dy) * 64 + pxb];
                        float4 q0 = *(const float4 *)(rowp + 0);
                        float4 q1 = *(const float4 *)(rowp + 4);
                        float2 q2 = *(const float2 *)(rowp + 8);
                        float f[10] = {q0.x,q0.y,q0.z,q0.w, q1.x,q1.y,q1.z,q1.w,
                                       q2.x,q2.y};
                        f32x2 wa = rw1[dy*3+0], wb = rw1[dy*3+1], wc = rw1[dy*3+2];
                        #pragma unroll
                        for (int j = 0; j < 8; j++) {
                            fma2(vd[j], pk2(f[j+0], f[j+0]), wa);
                            fma2(vd[j], pk2(f[j+1], f[j+1]), wb);
                            fma2(vd[j], pk2(f[j+2], f[j+2]), wc);
                        }
                    }
                    #pragma unroll
                    for (int j = 0; j < 8; j++) vd[j] = lky2(vd[j]);
                }
                if (saving) {
                    #pragma unroll
                    for (int j = 0; j < 8; j++) cw[j * 32 + lane] = vd[j];
                }
                fma2(acc[0], vm1,   w2a); fma2(acc[0], vd[0], w2b); fma2(acc[0], vd[1], w2c);
                fma2(acc[1], vd[1], w2a); fma2(acc[1], vd[2], w2b); fma2(acc[1], vd[3], w2c);
                fma2(acc[2], vd[3], w2a); fma2(acc[2], vd[4], w2b); fma2(acc[2], vd[5], w2c);
                fma2(acc[3], vd[5], w2a); fma2(acc[3], vd[6], w2b); fma2(acc[3], vd[7], w2c);
                fma2(acc[4], vd[7], w2a);
            }
        }

        #pragma unroll
        for (int o = 0; o < 8; o++) {
            float lo, hi; unpk2(acc[o], lo, hi);
            float s = lo + hi;
            s += __shfl_xor_sync(0xffffffffu, s, 1);
            s += __shfl_xor_sync(0xffffffffu, s, 2);
            s += __shfl_xor_sync(0xffffffffu, s, 4);
            if (cp == 0 && o < n_out)
                emb_s[im * EMB + i2 * 30 + 8 * xq + o] = lky(s + bias2);
        }
    }
    __syncthreads();

    float *eo = emb_out + (size_t)(2 * blockIdx.x) * EMB;
    for (int i = tid; i < 2 * EMB; i += 256) eo[i] = emb_s[i];
}

// =====================================================================
// K-split GEMM v4 (unchanged from R12): double-buffered k-loop.
// =====================================================================
__global__ void __launch_bounds__(256) gemm100_ks_kernel(
    const float *__restrict__ A, const float *__restrict__ W,
    const float *__restrict__ bias, float *__restrict__ C,
    int M, int K, int chunk)
{
    __shared__ __align__(16) float As[2][32][68];
    __shared__ __align__(16) float Ws[2][32][104];

    const int tid = threadIdx.x;
    const int row0 = blockIdx.x * 64;
    const int kbeg = blockIdx.y * chunk;
    const int kend = min(K, kbeg + chunk);
    float *Cout = C + (size_t)blockIdx.y * M * 100;
    const int tx = tid % 25;
    const int ty = tid / 25;
    const bool act = (tid < 200);
    const int nt = (kend - kbeg + 31) / 32;

    f32x2 acc[8][2];
    #pragma unroll
    for (int r = 0; r < 8; r++) { acc[r][0] = 0ull; acc[r][1] = 0ull; }

    {
        #pragma unroll
        for (int i = 0; i < 8; i++) {
            int e = tid + i * 256;
            int m = e >> 5, kk = e & 31;
            int k = kbeg + kk;
            As[0][kk][m] = (k < kend) ? A[(size_t)(row0 + m) * K + k] : 0.f;
        }
        #pragma unroll
        for (int i = 0; i < 13; i++) {
            int e = tid + i * 256;
            if (e < 3200) {
                int kk = e / 100, j = e % 100;
                int k = kbeg + kk;
                Ws[0][kk][j] = (k < kend) ? W[(size_t)k * 100 + j] : 0.f;
            }
        }
    }
    __syncthreads();

    #pragma unroll 1
    for (int t = 0; t < nt; t++) {
        const int cur = t & 1;
        const bool pre = (t + 1 < nt);
        float pa[8];
        float pw[13];
        if (pre) {
            const int k0n = kbeg + (t + 1) * 32;
            #pragma unroll
            for (int i = 0; i < 8; i++) {
                int e = tid + i * 256;
                int m = e >> 5, kk = e & 31;
                int k = k0n + kk;
                pa[i] = (k < kend) ? A[(size_t)(row0 + m) * K + k] : 0.f;
            }
            #pragma unroll
            for (int i = 0; i < 13; i++) {
                int e = tid + i * 256;
                if (e < 3200) {
                    int kk = e / 100, j = e % 100;
                    int k = k0n + kk;
                    pw[i] = (k < kend) ? W[(size_t)k * 100 + j] : 0.f;
                }
            }
        }
        if (act) {
            #pragma unroll
            for (int kk = 0; kk < 32; kk++) {
                f32x2 w0 = *(const f32x2 *)&Ws[cur][kk][4 * tx];
                f32x2 w1 = *(const f32x2 *)&Ws[cur][kk][4 * tx + 2];
                float4 a0 = *(const float4 *)&As[cur][kk][8 * ty];
                float4 a1 = *(const float4 *)&As[cur][kk][8 * ty + 4];
                float ar[8] = {a0.x, a0.y, a0.z, a0.w, a1.x, a1.y, a1.z, a1.w};
                #pragma unroll
                for (int r = 0; r < 8; r++) {
                    f32x2 aa = pk2(ar[r], ar[r]);
                    fma2(acc[r][0], aa, w0);
                    fma2(acc[r][1], aa, w1);
                }
            }
        }
        if (pre) {
            const int nxt = 1 - cur;
            #pragma unroll
            for (int i = 0; i < 8; i++) {
                int e = tid + i * 256;
                As[nxt][e & 31][e >> 5] = pa[i];
            }
            #pragma unroll
            for (int i = 0; i < 13; i++) {
                int e = tid + i * 256;
                if (e < 3200) Ws[nxt][e / 100][e % 100] = pw[i];
            }
            __syncthreads();
        }
    }

    if (act) {
        float b0 = 0.f, b1_ = 0.f, b2_ = 0.f, b3 = 0.f;
        if (blockIdx.y == 0) {
            b0 = bias[4 * tx + 0]; b1_ = bias[4 * tx + 1];
            b2_ = bias[4 * tx + 2]; b3 = bias[4 * tx + 3];
        }
        #pragma unroll
        for (int r = 0; r < 8; r++) {
            float x0, x1, x2, x3;
            unpk2(acc[r][0], x0, x1);
            unpk2(acc[r][1], x2, x3);
            float4 v = make_float4(x0 + b0, x1 + b1_, x2 + b2_, x3 + b3);
            *(float4 *)&Cout[(size_t)(row0 + 8 * ty + r) * 100 + 4 * tx] = v;
        }
    }
}

// =====================================================================
// Recurrence v2: 3 syncs per step.
//  P1: gemv1 partials (H(400)->100), 10 slices x 50 pairs  -> sync
//  P2: tid<100 reduce + tanh -> sRt                         -> sync
//  P3: warp-local gemv2 (Rt(100)->100): warp w owns pairs
//      p = w + 16i; lanes slice k with stride 32; 64-bit butterfly
//      reduce; lanes 0..7 apply tanh + 4-alpha H update + store -> sync
// =====================================================================
__global__ void __launch_bounds__(512) recurrence_kernel(
    const float *__restrict__ Rw, const float *__restrict__ Rb,
    const float *__restrict__ Qw, const float *__restrict__ E,
    float *__restrict__ Hall)
{
    __shared__ __align__(16) float sH[HSZ];
    __shared__ float sRt[QS];
    __shared__ __align__(16) float part[1008];
    __shared__ __align__(16) float sE[TT * QS];    // 25.6 KB

    const int tid = threadIdx.x;
    const int b   = blockIdx.x;
    const int wid = tid >> 5;
    const int lane = tid & 31;
    const int jp  = tid % 50;
    const int ks  = tid / 50;
    const bool act = (tid < 500);
    const size_t PSTRIDE = (size_t)NIMG * QS;

    // P1 weights (unchanged)
    f32x2 w1r[40];
    if (act) {
        #pragma unroll
        for (int kk = 0; kk < 40; kk++) {
            int k = ks * 40 + kk;
            w1r[kk] = *(const f32x2 *)&Rw[(size_t)k * 100 + 2 * jp];
        }
    }
    // P3 weights: pair i -> p = wid + 16*i (valid p < 50); lane covers
    // k = lane + 32*ii (valid k < 100)
    f32x2 w2r[4][4];
    #pragma unroll
    for (int i = 0; i < 4; i++) {
        int p = wid + 16 * i;
        #pragma unroll
        for (int ii = 0; ii < 4; ii++) {
            int k = lane + 32 * ii;
            w2r[i][ii] = (p < 50 && k < 100)
                ? *(const f32x2 *)&Qw[(size_t)(750 + k) * 100 + 2 * p] : 0ull;
        }
    }
    // preload summed E
    {
        const float *Eb = E + (size_t)b * TT * QS;
        for (int i = tid; i < TT * QS; i += 512) {
            float s = Eb[i];
            #pragma unroll
            for (int p = 1; p < KSPLIT; p++) s += Eb[p * PSTRIDE + i];
            sE[i] = s;
        }
    }
    for (int i = tid; i < HSZ; i += 512) sH[i] = 0.f;
    __syncthreads();

    float *Hb = Hall + (size_t)b * TT * HSZ;
    const float alphas[4] = {0.0f, 0.25f, 0.5f, 0.95f};

    #pragma unroll 1
    for (int t = 0; t < TT; t++) {
        // ---- P1: gemv1 partials ----
        if (act) {
            f32x2 a0 = 0ull, a1 = 0ull;
            #pragma unroll
            for (int kk = 0; kk < 40; kk += 2) {
                float h0 = sH[ks * 40 + kk];
                float h1 = sH[ks * 40 + kk + 1];
                fma2(a0, pk2(h0, h0), w1r[kk]);
                fma2(a1, pk2(h1, h1), w1r[kk + 1]);
            }
            *(f32x2 *)&part[ks * 100 + 2 * jp] = add2(a0, a1);
        }
        __syncthreads();
        // ---- P2: reduce + tanh -> sRt ----
        if (tid < 100) {
            float s = Rb[tid];
            #pragma unroll
            for (int ss = 0; ss < 10; ss++) s += part[ss * 100 + tid];
            sRt[tid] = tanhf(s);
        }
        __syncthreads();
        // ---- P3: warp-local gemv2 + tanh + H update ----
        #pragma unroll
        for (int i = 0; i < 4; i++) {
            const int p = wid + 16 * i;
            f32x2 a = 0ull;
            #pragma unroll
            for (int ii = 0; ii < 4; ii++) {
                int k = lane + 32 * ii;
                float r = (k < 100) ? sRt[k] : 0.f;
                fma2(a, pk2(r, r), w2r[i][ii]);
            }
            #pragma unroll
            for (int o = 16; o > 0; o >>= 1)
                a = add2(a, __shfl_xor_sync(0xffffffffu, a, o));
            if (p < 50 && lane < 8) {
                int ag = lane >> 1, jj = lane & 1;
                int j = 2 * p + jj;
                float lo, hi; unpk2(a, lo, hi);
                float q = tanhf((jj ? hi : lo) + sE[t * QS + j]);
                float al = alphas[ag];
                int idx = ag * 100 + j;
                float hn = al * sH[idx] + (1.f - al) * q;
                sH[idx] = hn;
                Hb[t * HSZ + idx] = hn;
            }
        }
        __syncthreads();
    }
}

// =====================================================================
// Logits + softmax (R12 version): tanh(sum of KSPLIT O-partials).
// =====================================================================
__global__ void __launch_bounds__(256) logits_kernel(
    const float *__restrict__ O, const float *__restrict__ OutW,
    const float *__restrict__ OutB, float *__restrict__ out)
{
    const int b = blockIdx.x, tid = threadIdx.x;
    const size_t base = (size_t)b * (TT * QS);
    const size_t PSTRIDE = (size_t)NIMG * QS;

    float acc[NCLS];
    #pragma unroll
    for (int c = 0; c < NCLS; c++) acc[c] = 0.f;

    for (int i = tid; i < TT * QS; i += 256) {
        float s = 0.f;
        #pragma unroll
        for (int p = 0; p < KSPLIT; p++) s += O[p * PSTRIDE + base + i];
        float v = tanhf(s);
        const float *wr = OutW + (size_t)i * NCLS;
        #pragma unroll
        for (int c = 0; c < NCLS; c++) acc[c] += v * wr[c];
    }
    #pragma unroll
    for (int c = 0; c < NCLS; c++)
        #pragma unroll
        for (int o = 16; o > 0; o >>= 1)
            acc[c] += __shfl_down_sync(0xffffffffu, acc[c], o);

    __shared__ float wpart[8][NCLS];
    int w = tid >> 5, l = tid & 31;
    if (l == 0)
        #pragma unroll
        for (int c = 0; c < NCLS; c++) wpart[w][c] = acc[c];
    __syncthreads();

    __shared__ float slog[NCLS];
    if (tid < NCLS) {
        float s = OutB[tid];
        #pragma unroll
        for (int ww = 0; ww < 8; ww++) s += wpart[ww][tid];
        slog[tid] = s;
    }
    __syncthreads();
    __shared__ float smax, ssum;
    if (tid == 0) {
        float m = slog[0];
        #pragma unroll
        for (int c = 1; c < NCLS; c++) m = fmaxf(m, slog[c]);
        float su = 0.f;
        #pragma unroll
        for (int c = 0; c < NCLS; c++) su += expf(slog[c] - m);
        smax = m; ssum = su;
    }
    __syncthreads();
    if (tid < NCLS) out[(size_t)b * NCLS + tid] = expf(slog[tid] - smax) / ssum;
}

// =====================================================================
extern "C" void kernel_launch(void *const *d_in, const int *in_sizes, int n_in,
                              void *d_out, int out_size)
{
    const float *In     = (const float *)d_in[0];
    const float *conv1w = (const float *)d_in[1];
    const float *conv1b = (const float *)d_in[2];
    const float *conv2w = (const float *)d_in[3];
    const float *conv2b = (const float *)d_in[4];
    const float *Rw     = (const float *)d_in[5];
    const float *Rb     = (const float *)d_in[6];
    const float *Qw     = (const float *)d_in[7];
    const float *Qb     = (const float *)d_in[8];
    const float *Ow     = (const float *)d_in[9];
    const float *Obias  = (const float *)d_in[10];
    const float *OutW   = (const float *)d_in[11];
    const float *OutB   = (const float *)d_in[12];
    float *out = (float *)d_out;

    float *emb, *E, *Hall, *OutAll;
    cudaGetSymbolAddress((void **)&emb,    g_emb);
    cudaGetSymbolAddress((void **)&E,      g_E);
    cudaGetSymbolAddress((void **)&Hall,   g_Hall);
    cudaGetSymbolAddress((void **)&OutAll, g_OutAll);

    cudaFuncSetAttribute(conv_embed_kernel,
                         cudaFuncAttributeMaxDynamicSharedMemorySize, CONV_SMEM);

    // 1 nop: ncu capture (4th launch) lands on the recurrence
    nop_kernel_a<<<1, 32>>>();

    conv_embed_kernel<<<NIMG / 2, 256, CONV_SMEM>>>(In, conv1w, conv1b, conv2w, conv2b, emb);

    gemm100_ks_kernel<<<dim3(NIMG / 64, KSPLIT), 256>>>(emb, Qw, Qb, E, NIMG, EMB, 384);

    recurrence_kernel<<<BB, 512>>>(Rw, Rb, Qw, E, Hall);

    gemm100_ks_kernel<<<dim3(NIMG / 64, KSPLIT), 256>>>(Hall, Ow, Obias, OutAll, NIMG, HSZ, 224);

    logits_kernel<<<BB, 256>>>(OutAll, OutW, OutB, out);
}

// round 15
// speedup vs baseline: 1.1279x; 1.1279x over previous
#include <cuda_runtime.h>
#include <cuda_bf16.h>
#include <math.h>

// ---------------- problem constants ----------------
#define BB   128
#define TT   64
#define NIMG (BB*TT)          // 8192
#define HI   50
#define WI   60
#define HO   25
#define WO   30
#define EMB  750
#define QS   100
#define HSZ  400
#define NCLS 10
#define KSPLIT 2
#define PIMG_SZ (52 * 64 + 16)     // 3344 floats per padded image

// conv dynamic SMEM layout (bytes)
#define CONV_PIMG_OFF  0
#define CONV_CARRY_OFF (2 * PIMG_SZ * 4)                    // 26752
#define CONV_EMB_OFF   (CONV_CARRY_OFF + 8 * 16 * 32 * 8)   // +32768 = 59520
#define CONV_W_OFF     (CONV_EMB_OFF + 2 * EMB * 4)         // +6000  = 65520
#define CONV_SMEM      (CONV_W_OFF + (72 + 72 + 8) * 8)     // +1216  = 66736

// ---------------- f32x2 packed helpers ----------------
typedef unsigned long long f32x2;

__device__ __forceinline__ f32x2 pk2(float x, float y) {
    f32x2 r; asm("mov.b64 %0, {%1, %2};" : "=l"(r) : "f"(x), "f"(y)); return r;
}
__device__ __forceinline__ void unpk2(f32x2 v, float &x, float &y) {
    asm("mov.b64 {%0, %1}, %2;" : "=f"(x), "=f"(y) : "l"(v));
}
__device__ __forceinline__ void fma2(f32x2 &d, f32x2 a, f32x2 b) {
    asm("fma.rn.f32x2 %0, %1, %2, %0;" : "+l"(d) : "l"(a), "l"(b));
}
__device__ __forceinline__ f32x2 mul2(f32x2 a, f32x2 b) {
    f32x2 d; asm("mul.rn.f32x2 %0, %1, %2;" : "=l"(d) : "l"(a), "l"(b)); return d;
}
__device__ __forceinline__ f32x2 add2(f32x2 a, f32x2 b) {
    f32x2 d; asm("add.rn.f32x2 %0, %1, %2;" : "=l"(d) : "l"(a), "l"(b)); return d;
}
__device__ __forceinline__ float lky(float x) { return fmaxf(x, 0.01f * x); }
// packed leaky: 0.505*x + 0.495*|x|
__device__ __forceinline__ f32x2 lky2(f32x2 x) {
    f32x2 a = x & 0x7FFFFFFF7FFFFFFFULL;
    f32x2 r = mul2(x, pk2(0.505f, 0.505f));
    fma2(r, a, pk2(0.495f, 0.495f));
    return r;
}

// ---------------- scratch (static device memory; allowed) ----------------
__device__ float g_emb[NIMG * EMB];               // 24.6 MB
__device__ float g_E[KSPLIT * NIMG * QS];         //  6.6 MB (K-split partials)
__device__ float g_Hall[NIMG * HSZ];              // 13.1 MB
__device__ float g_OutAll[KSPLIT * NIMG * QS];    //  6.6 MB (K-split partials)

// ---------------- no-op kernel: keep ncu capture on recurrence ----------------
__global__ void nop_kernel_a() {}

// =====================================================================
// Conv v7 (unchanged from R12): strip + SMEM carry, 2 images per CTA.
// =====================================================================
__global__ void __launch_bounds__(256, 3) conv_embed_kernel(
    const float *__restrict__ In,
    const float *__restrict__ w1, const float *__restrict__ b1,
    const float *__restrict__ w2, const float *__restrict__ b2,
    float *__restrict__ emb_out)
{
    extern __shared__ char smraw[];
    float *pimg  = (float *)(smraw + CONV_PIMG_OFF);   // [2][PIMG_SZ]
    f32x2 *carry = (f32x2 *)(smraw + CONV_CARRY_OFF);  // [8][16][32]
    float *emb_s = (float *)(smraw + CONV_EMB_OFF);    // [2][EMB]
    f32x2 *sw1   = (f32x2 *)(smraw + CONV_W_OFF);      // [9*8]
    f32x2 *sw2   = sw1 + 72;                            // [9*8]
    f32x2 *sb1   = sw2 + 72;                            // [8]

    const int tid = threadIdx.x;
    const int wid = tid >> 5;
    const int lane = tid & 31;
    const int cp = lane & 7;
    const int xq = lane >> 3;
    const float *imgg0 = In + (size_t)(2 * blockIdx.x) * (HI * WI);

    for (int i = tid; i < 2 * PIMG_SZ; i += 256) {
        int im = (i >= PIMG_SZ) ? 1 : 0;
        int idx = i - im * PIMG_SZ;
        int pr = idx >> 6, pc = idx & 63;
        int r = pr - 1, x = pc - 1;
        float v = (idx < 52 * 64 && r >= 0 && r < HI && x >= 0 && x < WI)
                  ? imgg0[(size_t)im * (HI * WI) + r * WI + x] : 0.f;
        pimg[im * PIMG_SZ + idx] = v;
    }
    if (tid < 72) {
        int tap = tid / 8, c = tid % 8;
        sw1[tid] = pk2(w1[(2 * c) * 9 + tap], w1[(2 * c + 1) * 9 + tap]);
        sw2[tid] = pk2(w2[(2 * c) * 9 + tap], w2[(2 * c + 1) * 9 + tap]);
    }
    if (tid < 8) sb1[tid] = pk2(b1[2 * tid], b1[2 * tid + 1]);
    const float bias2 = b2[0];
    __syncthreads();

    f32x2 rw1[9];
    #pragma unroll
    for (int t = 0; t < 9; t++) rw1[t] = sw1[t * 8 + cp];
    const f32x2 rb1 = sb1[cp];

    const int n_out = (xq == 3) ? 6 : 8;
    const int pxb = 16 * xq;

    const int im = wid >> 2;
    const int wl = wid & 3;
    const int s0 = (wl == 0) ? 0 : (7 + 6 * (wl - 1));
    const int len = (wl == 0) ? 7 : 6;
    const float *P = pimg + im * PIMG_SZ;
    f32x2 *cw = carry + wid * (16 * 32);

    #pragma unroll 1
    for (int ii = 0; ii < len; ii++) {
        const int i2 = s0 + ii;
        f32x2 acc[8];
        #pragma unroll
        for (int o = 0; o < 8; o++) acc[o] = 0ull;

        #pragma unroll 1
        for (int dy2 = 0; dy2 < 3; dy2++) {
            const int r = 2 * i2 - 1 + dy2;
            const bool restore = (dy2 == 0) && (ii > 0);
            const bool have = restore || (r >= 0);
            const bool saving = (dy2 == 2) && (ii + 1 < len);
            f32x2 w2a = sw2[(dy2 * 3 + 0) * 8 + cp];
            f32x2 w2b = sw2[(dy2 * 3 + 1) * 8 + cp];
            f32x2 w2c = sw2[(dy2 * 3 + 2) * 8 + cp];
            f32x2 vtop = 0ull;

            if (have) {
                f32x2 vc[8];
                if (restore) {
                    #pragma unroll
                    for (int j = 0; j < 8; j++) vc[j] = cw[(8 + j) * 32 + lane];
                } else {
                    #pragma unroll
                    for (int j = 0; j < 8; j++) vc[j] = rb1;
                    #pragma unroll
                    for (int dy = 0; dy < 3; dy++) {
                        const float *rowp = &P[(r + dy) * 64 + pxb + 8];
                        float4 q0 = *(const float4 *)(rowp + 0);
                        float4 q1 = *(const float4 *)(rowp + 4);
                        float2 q2 = *(const float2 *)(rowp + 8);
                        float f[10] = {q0.x,q0.y,q0.z,q0.w, q1.x,q1.y,q1.z,q1.w,
                                       q2.x,q2.y};
                        f32x2 wa = rw1[dy*3+0], wb = rw1[dy*3+1], wc = rw1[dy*3+2];
                        #pragma unroll
                        for (int j = 0; j < 8; j++) {
                            fma2(vc[j], pk2(f[j+0], f[j+0]), wa);
                            fma2(vc[j], pk2(f[j+1], f[j+1]), wb);
                            fma2(vc[j], pk2(f[j+2], f[j+2]), wc);
                        }
                    }
                    #pragma unroll
                    for (int j = 0; j < 8; j++) vc[j] = lky2(vc[j]);
                }
                if (saving) {
                    #pragma unroll
                    for (int j = 0; j < 8; j++) cw[(8 + j) * 32 + lane] = vc[j];
                }
                fma2(acc[4], vc[0], w2b); fma2(acc[4], vc[1], w2c);
                fma2(acc[5], vc[1], w2a); fma2(acc[5], vc[2], w2b); fma2(acc[5], vc[3], w2c);
                fma2(acc[6], vc[3], w2a); fma2(acc[6], vc[4], w2b); fma2(acc[6], vc[5], w2c);
                fma2(acc[7], vc[5], w2a); fma2(acc[7], vc[6], w2b); fma2(acc[7], vc[7], w2c);
                vtop = vc[7];
            }

            f32x2 vm1 = __shfl_up_sync(0xffffffffu, vtop, 8);
            if (xq == 0) vm1 = 0ull;

            if (have) {
                f32x2 vd[8];
                if (restore) {
                    #pragma unroll
                    for (int j = 0; j < 8; j++) vd[j] = cw[j * 32 + lane];
                } else {
                    #pragma unroll
                    for (int j = 0; j < 8; j++) vd[j] = rb1;
                    #pragma unroll
                    for (int dy = 0; dy < 3; dy++) {
                        const float *rowp = &P[(r + dy) * 64 + pxb];
                        float4 q0 = *(const float4 *)(rowp + 0);
                        float4 q1 = *(const float4 *)(rowp + 4);
                        float2 q2 = *(const float2 *)(rowp + 8);
                        float f[10] = {q0.x,q0.y,q0.z,q0.w, q1.x,q1.y,q1.z,q1.w,
                                       q2.x,q2.y};
                        f32x2 wa = rw1[dy*3+0], wb = rw1[dy*3+1], wc = rw1[dy*3+2];
                        #pragma unroll
                        for (int j = 0; j < 8; j++) {
                            fma2(vd[j], pk2(f[j+0], f[j+0]), wa);
                            fma2(vd[j], pk2(f[j+1], f[j+1]), wb);
                            fma2(vd[j], pk2(f[j+2], f[j+2]), wc);
                        }
                    }
                    #pragma unroll
                    for (int j = 0; j < 8; j++) vd[j] = lky2(vd[j]);
                }
                if (saving) {
                    #pragma unroll
                    for (int j = 0; j < 8; j++) cw[j * 32 + lane] = vd[j];
                }
                fma2(acc[0], vm1,   w2a); fma2(acc[0], vd[0], w2b); fma2(acc[0], vd[1], w2c);
                fma2(acc[1], vd[1], w2a); fma2(acc[1], vd[2], w2b); fma2(acc[1], vd[3], w2c);
                fma2(acc[2], vd[3], w2a); fma2(acc[2], vd[4], w2b); fma2(acc[2], vd[5], w2c);
                fma2(acc[3], vd[5], w2a); fma2(acc[3], vd[6], w2b); fma2(acc[3], vd[7], w2c);
                fma2(acc[4], vd[7], w2a);
            }
        }

        #pragma unroll
        for (int o = 0; o < 8; o++) {
            float lo, hi; unpk2(acc[o], lo, hi);
            float s = lo + hi;
            s += __shfl_xor_sync(0xffffffffu, s, 1);
            s += __shfl_xor_sync(0xffffffffu, s, 2);
            s += __shfl_xor_sync(0xffffffffu, s, 4);
            if (cp == 0 && o < n_out)
                emb_s[im * EMB + i2 * 30 + 8 * xq + o] = lky(s + bias2);
        }
    }
    __syncthreads();

    float *eo = emb_out + (size_t)(2 * blockIdx.x) * EMB;
    for (int i = tid; i < 2 * EMB; i += 256) eo[i] = emb_s[i];
}

// =====================================================================
// K-split GEMM v4 (unchanged from R12): double-buffered k-loop.
// =====================================================================
__global__ void __launch_bounds__(256) gemm100_ks_kernel(
    const float *__restrict__ A, const float *__restrict__ W,
    const float *__restrict__ bias, float *__restrict__ C,
    int M, int K, int chunk)
{
    __shared__ __align__(16) float As[2][32][68];
    __shared__ __align__(16) float Ws[2][32][104];

    const int tid = threadIdx.x;
    const int row0 = blockIdx.x * 64;
    const int kbeg = blockIdx.y * chunk;
    const int kend = min(K, kbeg + chunk);
    float *Cout = C + (size_t)blockIdx.y * M * 100;
    const int tx = tid % 25;
    const int ty = tid / 25;
    const bool act = (tid < 200);
    const int nt = (kend - kbeg + 31) / 32;

    f32x2 acc[8][2];
    #pragma unroll
    for (int r = 0; r < 8; r++) { acc[r][0] = 0ull; acc[r][1] = 0ull; }

    {
        #pragma unroll
        for (int i = 0; i < 8; i++) {
            int e = tid + i * 256;
            int m = e >> 5, kk = e & 31;
            int k = kbeg + kk;
            As[0][kk][m] = (k < kend) ? A[(size_t)(row0 + m) * K + k] : 0.f;
        }
        #pragma unroll
        for (int i = 0; i < 13; i++) {
            int e = tid + i * 256;
            if (e < 3200) {
                int kk = e / 100, j = e % 100;
                int k = kbeg + kk;
                Ws[0][kk][j] = (k < kend) ? W[(size_t)k * 100 + j] : 0.f;
            }
        }
    }
    __syncthreads();

    #pragma unroll 1
    for (int t = 0; t < nt; t++) {
        const int cur = t & 1;
        const bool pre = (t + 1 < nt);
        float pa[8];
        float pw[13];
        if (pre) {
            const int k0n = kbeg + (t + 1) * 32;
            #pragma unroll
            for (int i = 0; i < 8; i++) {
                int e = tid + i * 256;
                int m = e >> 5, kk = e & 31;
                int k = k0n + kk;
                pa[i] = (k < kend) ? A[(size_t)(row0 + m) * K + k] : 0.f;
            }
            #pragma unroll
            for (int i = 0; i < 13; i++) {
                int e = tid + i * 256;
                if (e < 3200) {
                    int kk = e / 100, j = e % 100;
                    int k = k0n + kk;
                    pw[i] = (k < kend) ? W[(size_t)k * 100 + j] : 0.f;
                }
            }
        }
        if (act) {
            #pragma unroll
            for (int kk = 0; kk < 32; kk++) {
                f32x2 w0 = *(const f32x2 *)&Ws[cur][kk][4 * tx];
                f32x2 w1 = *(const f32x2 *)&Ws[cur][kk][4 * tx + 2];
                float4 a0 = *(const float4 *)&As[cur][kk][8 * ty];
                float4 a1 = *(const float4 *)&As[cur][kk][8 * ty + 4];
                float ar[8] = {a0.x, a0.y, a0.z, a0.w, a1.x, a1.y, a1.z, a1.w};
                #pragma unroll
                for (int r = 0; r < 8; r++) {
                    f32x2 aa = pk2(ar[r], ar[r]);
                    fma2(acc[r][0], aa, w0);
                    fma2(acc[r][1], aa, w1);
                }
            }
        }
        if (pre) {
            const int nxt = 1 - cur;
            #pragma unroll
            for (int i = 0; i < 8; i++) {
                int e = tid + i * 256;
                As[nxt][e & 31][e >> 5] = pa[i];
            }
            #pragma unroll
            for (int i = 0; i < 13; i++) {
                int e = tid + i * 256;
                if (e < 3200) Ws[nxt][e / 100][e % 100] = pw[i];
            }
            __syncthreads();
        }
    }

    if (act) {
        float b0 = 0.f, b1_ = 0.f, b2_ = 0.f, b3 = 0.f;
        if (blockIdx.y == 0) {
            b0 = bias[4 * tx + 0]; b1_ = bias[4 * tx + 1];
            b2_ = bias[4 * tx + 2]; b3 = bias[4 * tx + 3];
        }
        #pragma unroll
        for (int r = 0; r < 8; r++) {
            float x0, x1, x2, x3;
            unpk2(acc[r][0], x0, x1);
            unpk2(acc[r][1], x2, x3);
            float4 v = make_float4(x0 + b0, x1 + b1_, x2 + b2_, x3 + b3);
            *(float4 *)&Cout[(size_t)(row0 + 8 * ty + r) * 100 + 4 * tx] = v;
        }
    }
}

// =====================================================================
// Recurrence (R12 structure; P1 sH reads vectorized to LDS.128).
// =====================================================================
__global__ void __launch_bounds__(512) recurrence_kernel(
    const float *__restrict__ Rw, const float *__restrict__ Rb,
    const float *__restrict__ Qw, const float *__restrict__ E,
    float *__restrict__ Hall)
{
    __shared__ __align__(16) float sH[HSZ];
    __shared__ float sRt[QS];
    __shared__ __align__(16) float part[1008];
    __shared__ __align__(16) float sE[TT * QS];    // 25.6 KB

    const int tid = threadIdx.x;
    const int b   = blockIdx.x;
    const int jp  = tid % 50;
    const int ks  = tid / 50;
    const bool act = (tid < 500);
    const size_t PSTRIDE = (size_t)NIMG * QS;

    f32x2 w1r[40];
    f32x2 w2r[10];
    if (act) {
        #pragma unroll
        for (int kk = 0; kk < 40; kk++) {
            int k = ks * 40 + kk;
            w1r[kk] = *(const f32x2 *)&Rw[(size_t)k * 100 + 2 * jp];
        }
        #pragma unroll
        for (int kk = 0; kk < 10; kk++) {
            int k = ks * 10 + kk;
            w2r[kk] = *(const f32x2 *)&Qw[(size_t)(750 + k) * 100 + 2 * jp];
        }
    }
    {
        const float *Eb = E + (size_t)b * TT * QS;
        for (int i = tid; i < TT * QS; i += 512) {
            float s = Eb[i];
            #pragma unroll
            for (int p = 1; p < KSPLIT; p++) s += Eb[p * PSTRIDE + i];
            sE[i] = s;
        }
    }
    for (int i = tid; i < HSZ; i += 512) sH[i] = 0.f;
    __syncthreads();

    float *Hb = Hall + (size_t)b * TT * HSZ;

    #pragma unroll 1
    for (int t = 0; t < TT; t++) {
        // ---- P1: gemv1 partials; sH via LDS.128 (ks*40 is 160B-aligned) ----
        if (act) {
            const float4 *sH4 = (const float4 *)&sH[ks * 40];
            f32x2 a0 = 0ull, a1 = 0ull;
            #pragma unroll
            for (int q = 0; q < 10; q++) {
                float4 h = sH4[q];
                fma2(a0, pk2(h.x, h.x), w1r[4 * q + 0]);
                fma2(a1, pk2(h.y, h.y), w1r[4 * q + 1]);
                fma2(a0, pk2(h.z, h.z), w1r[4 * q + 2]);
                fma2(a1, pk2(h.w, h.w), w1r[4 * q + 3]);
            }
            *(f32x2 *)&part[ks * 100 + 2 * jp] = add2(a0, a1);
        }
        __syncthreads();
        if (tid < 100) {
            float s = Rb[tid];
            #pragma unroll
            for (int ss = 0; ss < 10; ss++) s += part[ss * 100 + tid];
            sRt[tid] = tanhf(s);
        }
        __syncthreads();
        if (act) {
            f32x2 a = 0ull;
            #pragma unroll
            for (int kk = 0; kk < 10; kk++) {
                float h = sRt[ks * 10 + kk];
                fma2(a, pk2(h, h), w2r[kk]);
            }
            *(f32x2 *)&part[ks * 100 + 2 * jp] = a;
        }
        __syncthreads();
        if (tid < HSZ) {
            int j = tid % 100;
            float s = sE[t * QS + j];
            #pragma unroll
            for (int ss = 0; ss < 10; ss++) s += part[ss * 100 + j];
            float q = tanhf(s);
            const float alphas[4] = {0.0f, 0.25f, 0.5f, 0.95f};
            float al = alphas[tid / 100];
            float hn = al * sH[tid] + (1.f - al) * q;
            sH[tid] = hn;
            Hb[t * HSZ + tid] = hn;
        }
        __syncthreads();
    }
}

// =====================================================================
// Logits + softmax (R12 version): tanh(sum of KSPLIT O-partials).
// =====================================================================
__global__ void __launch_bounds__(256) logits_kernel(
    const float *__restrict__ O, const float *__restrict__ OutW,
    const float *__restrict__ OutB, float *__restrict__ out)
{
    const int b = blockIdx.x, tid = threadIdx.x;
    const size_t base = (size_t)b * (TT * QS);
    const size_t PSTRIDE = (size_t)NIMG * QS;

    float acc[NCLS];
    #pragma unroll
    for (int c = 0; c < NCLS; c++) acc[c] = 0.f;

    for (int i = tid; i < TT * QS; i += 256) {
        float s = 0.f;
        #pragma unroll
        for (int p = 0; p < KSPLIT; p++) s += O[p * PSTRIDE + base + i];
        float v = tanhf(s);
        const float *wr = OutW + (size_t)i * NCLS;
        #pragma unroll
        for (int c = 0; c < NCLS; c++) acc[c] += v * wr[c];
    }
    #pragma unroll
    for (int c = 0; c < NCLS; c++)
        #pragma unroll
        for (int o = 16; o > 0; o >>= 1)
            acc[c] += __shfl_down_sync(0xffffffffu, acc[c], o);

    __shared__ float wpart[8][NCLS];
    int w = tid >> 5, l = tid & 31;
    if (l == 0)
        #pragma unroll
        for (int c = 0; c < NCLS; c++) wpart[w][c] = acc[c];
    __syncthreads();

    __shared__ float slog[NCLS];
    if (tid < NCLS) {
        float s = OutB[tid];
        #pragma unroll
        for (int ww = 0; ww < 8; ww++) s += wpart[ww][tid];
        slog[tid] = s;
    }
    __syncthreads();
    __shared__ float smax, ssum;
    if (tid == 0) {
        float m = slog[0];
        #pragma unroll
        for (int c = 1; c < NCLS; c++) m = fmaxf(m, slog[c]);
        float su = 0.f;
        #pragma unroll
        for (int c = 0; c < NCLS; c++) su += expf(slog[c] - m);
        smax = m; ssum = su;
    }
    __syncthreads();
    if (tid < NCLS) out[(size_t)b * NCLS + tid] = expf(slog[tid] - smax) / ssum;
}

// =====================================================================
extern "C" void kernel_launch(void *const *d_in, const int *in_sizes, int n_in,
                              void *d_out, int out_size)
{
    const float *In     = (const float *)d_in[0];
    const float *conv1w = (const float *)d_in[1];
    const float *conv1b = (const float *)d_in[2];
    const float *conv2w = (const float *)d_in[3];
    const float *conv2b = (const float *)d_in[4];
    const float *Rw     = (const float *)d_in[5];
    const float *Rb     = (const float *)d_in[6];
    const float *Qw     = (const float *)d_in[7];
    const float *Qb     = (const float *)d_in[8];
    const float *Ow     = (const float *)d_in[9];
    const float *Obias  = (const float *)d_in[10];
    const float *OutW   = (const float *)d_in[11];
    const float *OutB   = (const float *)d_in[12];
    float *out = (float *)d_out;

    float *emb, *E, *Hall, *OutAll;
    cudaGetSymbolAddress((void **)&emb,    g_emb);
    cudaGetSymbolAddress((void **)&E,      g_E);
    cudaGetSymbolAddress((void **)&Hall,   g_Hall);
    cudaGetSymbolAddress((void **)&OutAll, g_OutAll);

    cudaFuncSetAttribute(conv_embed_kernel,
                         cudaFuncAttributeMaxDynamicSharedMemorySize, CONV_SMEM);

    // 1 nop: ncu capture (4th launch) lands on the recurrence
    nop_kernel_a<<<1, 32>>>();

    conv_embed_kernel<<<NIMG / 2, 256, CONV_SMEM>>>(In, conv1w, conv1b, conv2w, conv2b, emb);

    gemm100_ks_kernel<<<dim3(NIMG / 64, KSPLIT), 256>>>(emb, Qw, Qb, E, NIMG, EMB, 384);

    recurrence_kernel<<<BB, 512>>>(Rw, Rb, Qw, E, Hall);

    gemm100_ks_kernel<<<dim3(NIMG / 64, KSPLIT), 256>>>(Hall, Ow, Obias, OutAll, NIMG, HSZ, 224);

    logits_kernel<<<BB, 256>>>(OutAll, OutW, OutB, out);
}

// round 16
// speedup vs baseline: 1.1403x; 1.0110x over previous
#include <cuda_runtime.h>
#include <cuda_bf16.h>
#include <math.h>

// ---------------- problem constants ----------------
#define BB   128
#define TT   64
#define NIMG (BB*TT)          // 8192
#define HI   50
#define WI   60
#define HO   25
#define WO   30
#define EMB  750
#define QS   100
#define HSZ  400
#define NCLS 10
#define KSPLIT_E 3
#define KSPLIT_O 2
#define PIMG_SZ (52 * 64 + 16)     // 3344 floats per padded image

// conv dynamic SMEM layout (bytes)
#define CONV_PIMG_OFF  0
#define CONV_CARRY_OFF (2 * PIMG_SZ * 4)                    // 26752
#define CONV_EMB_OFF   (CONV_CARRY_OFF + 8 * 16 * 32 * 8)   // +32768 = 59520
#define CONV_W_OFF     (CONV_EMB_OFF + 2 * EMB * 4)         // +6000  = 65520
#define CONV_SMEM      (CONV_W_OFF + (72 + 72 + 8) * 8)     // +1216  = 66736

// ---------------- f32x2 packed helpers ----------------
typedef unsigned long long f32x2;

__device__ __forceinline__ f32x2 pk2(float x, float y) {
    f32x2 r; asm("mov.b64 %0, {%1, %2};" : "=l"(r) : "f"(x), "f"(y)); return r;
}
__device__ __forceinline__ void unpk2(f32x2 v, float &x, float &y) {
    asm("mov.b64 {%0, %1}, %2;" : "=f"(x), "=f"(y) : "l"(v));
}
__device__ __forceinline__ void fma2(f32x2 &d, f32x2 a, f32x2 b) {
    asm("fma.rn.f32x2 %0, %1, %2, %0;" : "+l"(d) : "l"(a), "l"(b));
}
__device__ __forceinline__ f32x2 mul2(f32x2 a, f32x2 b) {
    f32x2 d; asm("mul.rn.f32x2 %0, %1, %2;" : "=l"(d) : "l"(a), "l"(b)); return d;
}
__device__ __forceinline__ f32x2 add2(f32x2 a, f32x2 b) {
    f32x2 d; asm("add.rn.f32x2 %0, %1, %2;" : "=l"(d) : "l"(a), "l"(b)); return d;
}
__device__ __forceinline__ float lky(float x) { return fmaxf(x, 0.01f * x); }
// packed leaky: 0.505*x + 0.495*|x|
__device__ __forceinline__ f32x2 lky2(f32x2 x) {
    f32x2 a = x & 0x7FFFFFFF7FFFFFFFULL;
    f32x2 r = mul2(x, pk2(0.505f, 0.505f));
    fma2(r, a, pk2(0.495f, 0.495f));
    return r;
}

// ---------------- scratch (static device memory; allowed) ----------------
__device__ float g_emb[NIMG * EMB];                 // 24.6 MB
__device__ float g_E[KSPLIT_E * NIMG * QS];         //  9.8 MB (K-split partials)
__device__ float g_Hall[NIMG * HSZ];                // 13.1 MB
__device__ float g_OutAll[KSPLIT_O * NIMG * QS];    //  6.6 MB (K-split partials)
__device__ float g_lgpart[2 * BB * NCLS];           // logits partials (i halves)

// ---------------- no-op kernels: ncu capture lands on the E-GEMM ----------------
__global__ void nop_kernel_a() {}
__global__ void nop_kernel_b() {}

// =====================================================================
// Conv v7 (unchanged from R12): strip + SMEM carry, 2 images per CTA.
// =====================================================================
__global__ void __launch_bounds__(256, 3) conv_embed_kernel(
    const float *__restrict__ In,
    const float *__restrict__ w1, const float *__restrict__ b1,
    const float *__restrict__ w2, const float *__restrict__ b2,
    float *__restrict__ emb_out)
{
    extern __shared__ char smraw[];
    float *pimg  = (float *)(smraw + CONV_PIMG_OFF);   // [2][PIMG_SZ]
    f32x2 *carry = (f32x2 *)(smraw + CONV_CARRY_OFF);  // [8][16][32]
    float *emb_s = (float *)(smraw + CONV_EMB_OFF);    // [2][EMB]
    f32x2 *sw1   = (f32x2 *)(smraw + CONV_W_OFF);      // [9*8]
    f32x2 *sw2   = sw1 + 72;                            // [9*8]
    f32x2 *sb1   = sw2 + 72;                            // [8]

    const int tid = threadIdx.x;
    const int wid = tid >> 5;
    const int lane = tid & 31;
    const int cp = lane & 7;
    const int xq = lane >> 3;
    const float *imgg0 = In + (size_t)(2 * blockIdx.x) * (HI * WI);

    for (int i = tid; i < 2 * PIMG_SZ; i += 256) {
        int im = (i >= PIMG_SZ) ? 1 : 0;
        int idx = i - im * PIMG_SZ;
        int pr = idx >> 6, pc = idx & 63;
        int r = pr - 1, x = pc - 1;
        float v = (idx < 52 * 64 && r >= 0 && r < HI && x >= 0 && x < WI)
                  ? imgg0[(size_t)im * (HI * WI) + r * WI + x] : 0.f;
        pimg[im * PIMG_SZ + idx] = v;
    }
    if (tid < 72) {
        int tap = tid / 8, c = tid % 8;
        sw1[tid] = pk2(w1[(2 * c) * 9 + tap], w1[(2 * c + 1) * 9 + tap]);
        sw2[tid] = pk2(w2[(2 * c) * 9 + tap], w2[(2 * c + 1) * 9 + tap]);
    }
    if (tid < 8) sb1[tid] = pk2(b1[2 * tid], b1[2 * tid + 1]);
    const float bias2 = b2[0];
    __syncthreads();

    f32x2 rw1[9];
    #pragma unroll
    for (int t = 0; t < 9; t++) rw1[t] = sw1[t * 8 + cp];
    const f32x2 rb1 = sb1[cp];

    const int n_out = (xq == 3) ? 6 : 8;
    const int pxb = 16 * xq;

    const int im = wid >> 2;
    const int wl = wid & 3;
    const int s0 = (wl == 0) ? 0 : (7 + 6 * (wl - 1));
    const int len = (wl == 0) ? 7 : 6;
    const float *P = pimg + im * PIMG_SZ;
    f32x2 *cw = carry + wid * (16 * 32);

    #pragma unroll 1
    for (int ii = 0; ii < len; ii++) {
        const int i2 = s0 + ii;
        f32x2 acc[8];
        #pragma unroll
        for (int o = 0; o < 8; o++) acc[o] = 0ull;

        #pragma unroll 1
        for (int dy2 = 0; dy2 < 3; dy2++) {
            const int r = 2 * i2 - 1 + dy2;
            const bool restore = (dy2 == 0) && (ii > 0);
            const bool have = restore || (r >= 0);
            const bool saving = (dy2 == 2) && (ii + 1 < len);
            f32x2 w2a = sw2[(dy2 * 3 + 0) * 8 + cp];
            f32x2 w2b = sw2[(dy2 * 3 + 1) * 8 + cp];
            f32x2 w2c = sw2[(dy2 * 3 + 2) * 8 + cp];
            f32x2 vtop = 0ull;

            if (have) {
                f32x2 vc[8];
                if (restore) {
                    #pragma unroll
                    for (int j = 0; j < 8; j++) vc[j] = cw[(8 + j) * 32 + lane];
                } else {
                    #pragma unroll
                    for (int j = 0; j < 8; j++) vc[j] = rb1;
                    #pragma unroll
                    for (int dy = 0; dy < 3; dy++) {
                        const float *rowp = &P[(r + dy) * 64 + pxb + 8];
                        float4 q0 = *(const float4 *)(rowp + 0);
                        float4 q1 = *(const float4 *)(rowp + 4);
                        float2 q2 = *(const float2 *)(rowp + 8);
                        float f[10] = {q0.x,q0.y,q0.z,q0.w, q1.x,q1.y,q1.z,q1.w,
                                       q2.x,q2.y};
                        f32x2 wa = rw1[dy*3+0], wb = rw1[dy*3+1], wc = rw1[dy*3+2];
                        #pragma unroll
                        for (int j = 0; j < 8; j++) {
                            fma2(vc[j], pk2(f[j+0], f[j+0]), wa);
                            fma2(vc[j], pk2(f[j+1], f[j+1]), wb);
                            fma2(vc[j], pk2(f[j+2], f[j+2]), wc);
                        }
                    }
                    #pragma unroll
                    for (int j = 0; j < 8; j++) vc[j] = lky2(vc[j]);
                }
                if (saving) {
                    #pragma unroll
                    for (int j = 0; j < 8; j++) cw[(8 + j) * 32 + lane] = vc[j];
                }
                fma2(acc[4], vc[0], w2b); fma2(acc[4], vc[1], w2c);
                fma2(acc[5], vc[1], w2a); fma2(acc[5], vc[2], w2b); fma2(acc[5], vc[3], w2c);
                fma2(acc[6], vc[3], w2a); fma2(acc[6], vc[4], w2b); fma2(acc[6], vc[5], w2c);
                fma2(acc[7], vc[5], w2a); fma2(acc[7], vc[6], w2b); fma2(acc[7], vc[7], w2c);
                vtop = vc[7];
            }

            f32x2 vm1 = __shfl_up_sync(0xffffffffu, vtop, 8);
            if (xq == 0) vm1 = 0ull;

            if (have) {
                f32x2 vd[8];
                if (restore) {
                    #pragma unroll
                    for (int j = 0; j < 8; j++) vd[j] = cw[j * 32 + lane];
                } else {
                    #pragma unroll
                    for (int j = 0; j < 8; j++) vd[j] = rb1;
                    #pragma unroll
                    for (int dy = 0; dy < 3; dy++) {
                        const float *rowp = &P[(r + dy) * 64 + pxb];
                        float4 q0 = *(const float4 *)(rowp + 0);
                        float4 q1 = *(const float4 *)(rowp + 4);
                        float2 q2 = *(const float2 *)(rowp + 8);
                        float f[10] = {q0.x,q0.y,q0.z,q0.w, q1.x,q1.y,q1.z,q1.w,
                                       q2.x,q2.y};
                        f32x2 wa = rw1[dy*3+0], wb = rw1[dy*3+1], wc = rw1[dy*3+2];
                        #pragma unroll
                        for (int j = 0; j < 8; j++) {
                            fma2(vd[j], pk2(f[j+0], f[j+0]), wa);
                            fma2(vd[j], pk2(f[j+1], f[j+1]), wb);
                            fma2(vd[j], pk2(f[j+2], f[j+2]), wc);
                        }
                    }
                    #pragma unroll
                    for (int j = 0; j < 8; j++) vd[j] = lky2(vd[j]);
                }
                if (saving) {
                    #pragma unroll
                    for (int j = 0; j < 8; j++) cw[j * 32 + lane] = vd[j];
                }
                fma2(acc[0], vm1,   w2a); fma2(acc[0], vd[0], w2b); fma2(acc[0], vd[1], w2c);
                fma2(acc[1], vd[1], w2a); fma2(acc[1], vd[2], w2b); fma2(acc[1], vd[3], w2c);
                fma2(acc[2], vd[3], w2a); fma2(acc[2], vd[4], w2b); fma2(acc[2], vd[5], w2c);
                fma2(acc[3], vd[5], w2a); fma2(acc[3], vd[6], w2b); fma2(acc[3], vd[7], w2c);
                fma2(acc[4], vd[7], w2a);
            }
        }

        #pragma unroll
        for (int o = 0; o < 8; o++) {
            float lo, hi; unpk2(acc[o], lo, hi);
            float s = lo + hi;
            s += __shfl_xor_sync(0xffffffffu, s, 1);
            s += __shfl_xor_sync(0xffffffffu, s, 2);
            s += __shfl_xor_sync(0xffffffffu, s, 4);
            if (cp == 0 && o < n_out)
                emb_s[im * EMB + i2 * 30 + 8 * xq + o] = lky(s + bias2);
        }
    }
    __syncthreads();

    float *eo = emb_out + (size_t)(2 * blockIdx.x) * EMB;
    for (int i = tid; i < 2 * EMB; i += 256) eo[i] = emb_s[i];
}

// =====================================================================
// K-split GEMM v4 (unchanged from R12): double-buffered k-loop.
// =====================================================================
__global__ void __launch_bounds__(256) gemm100_ks_kernel(
    const float *__restrict__ A, const float *__restrict__ W,
    const float *__restrict__ bias, float *__restrict__ C,
    int M, int K, int chunk)
{
    __shared__ __align__(16) float As[2][32][68];
    __shared__ __align__(16) float Ws[2][32][104];

    const int tid = threadIdx.x;
    const int row0 = blockIdx.x * 64;
    const int kbeg = blockIdx.y * chunk;
    const int kend = min(K, kbeg + chunk);
    float *Cout = C + (size_t)blockIdx.y * M * 100;
    const int tx = tid % 25;
    const int ty = tid / 25;
    const bool act = (tid < 200);
    const int nt = (kend - kbeg + 31) / 32;

    f32x2 acc[8][2];
    #pragma unroll
    for (int r = 0; r < 8; r++) { acc[r][0] = 0ull; acc[r][1] = 0ull; }

    {
        #pragma unroll
        for (int i = 0; i < 8; i++) {
            int e = tid + i * 256;
            int m = e >> 5, kk = e & 31;
            int k = kbeg + kk;
            As[0][kk][m] = (k < kend) ? A[(size_t)(row0 + m) * K + k] : 0.f;
        }
        #pragma unroll
        for (int i = 0; i < 13; i++) {
            int e = tid + i * 256;
            if (e < 3200) {
                int kk = e / 100, j = e % 100;
                int k = kbeg + kk;
                Ws[0][kk][j] = (k < kend) ? W[(size_t)k * 100 + j] : 0.f;
            }
        }
    }
    __syncthreads();

    #pragma unroll 1
    for (int t = 0; t < nt; t++) {
        const int cur = t & 1;
        const bool pre = (t + 1 < nt);
        float pa[8];
        float pw[13];
        if (pre) {
            const int k0n = kbeg + (t + 1) * 32;
            #pragma unroll
            for (int i = 0; i < 8; i++) {
                int e = tid + i * 256;
                int m = e >> 5, kk = e & 31;
                int k = k0n + kk;
                pa[i] = (k < kend) ? A[(size_t)(row0 + m) * K + k] : 0.f;
            }
            #pragma unroll
            for (int i = 0; i < 13; i++) {
                int e = tid + i * 256;
                if (e < 3200) {
                    int kk = e / 100, j = e % 100;
                    int k = k0n + kk;
                    pw[i] = (k < kend) ? W[(size_t)k * 100 + j] : 0.f;
                }
            }
        }
        if (act) {
            #pragma unroll
            for (int kk = 0; kk < 32; kk++) {
                f32x2 w0 = *(const f32x2 *)&Ws[cur][kk][4 * tx];
                f32x2 w1 = *(const f32x2 *)&Ws[cur][kk][4 * tx + 2];
                float4 a0 = *(const float4 *)&As[cur][kk][8 * ty];
                float4 a1 = *(const float4 *)&As[cur][kk][8 * ty + 4];
                float ar[8] = {a0.x, a0.y, a0.z, a0.w, a1.x, a1.y, a1.z, a1.w};
                #pragma unroll
                for (int r = 0; r < 8; r++) {
                    f32x2 aa = pk2(ar[r], ar[r]);
                    fma2(acc[r][0], aa, w0);
                    fma2(acc[r][1], aa, w1);
                }
            }
        }
        if (pre) {
            const int nxt = 1 - cur;
            #pragma unroll
            for (int i = 0; i < 8; i++) {
                int e = tid + i * 256;
                As[nxt][e & 31][e >> 5] = pa[i];
            }
            #pragma unroll
            for (int i = 0; i < 13; i++) {
                int e = tid + i * 256;
                if (e < 3200) Ws[nxt][e / 100][e % 100] = pw[i];
            }
            __syncthreads();
        }
    }

    if (act) {
        float b0 = 0.f, b1_ = 0.f, b2_ = 0.f, b3 = 0.f;
        if (blockIdx.y == 0) {
            b0 = bias[4 * tx + 0]; b1_ = bias[4 * tx + 1];
            b2_ = bias[4 * tx + 2]; b3 = bias[4 * tx + 3];
        }
        #pragma unroll
        for (int r = 0; r < 8; r++) {
            float x0, x1, x2, x3;
            unpk2(acc[r][0], x0, x1);
            unpk2(acc[r][1], x2, x3);
            float4 v = make_float4(x0 + b0, x1 + b1_, x2 + b2_, x3 + b3);
            *(float4 *)&Cout[(size_t)(row0 + 8 * ty + r) * 100 + 4 * tx] = v;
        }
    }
}

// =====================================================================
// Recurrence (R15 version; sums KSPLIT_E E-partials in preload).
// =====================================================================
__global__ void __launch_bounds__(512) recurrence_kernel(
    const float *__restrict__ Rw, const float *__restrict__ Rb,
    const float *__restrict__ Qw, const float *__restrict__ E,
    float *__restrict__ Hall)
{
    __shared__ __align__(16) float sH[HSZ];
    __shared__ float sRt[QS];
    __shared__ __align__(16) float part[1008];
    __shared__ __align__(16) float sE[TT * QS];    // 25.6 KB

    const int tid = threadIdx.x;
    const int b   = blockIdx.x;
    const int jp  = tid % 50;
    const int ks  = tid / 50;
    const bool act = (tid < 500);
    const size_t PSTRIDE = (size_t)NIMG * QS;

    f32x2 w1r[40];
    f32x2 w2r[10];
    if (act) {
        #pragma unroll
        for (int kk = 0; kk < 40; kk++) {
            int k = ks * 40 + kk;
            w1r[kk] = *(const f32x2 *)&Rw[(size_t)k * 100 + 2 * jp];
        }
        #pragma unroll
        for (int kk = 0; kk < 10; kk++) {
            int k = ks * 10 + kk;
            w2r[kk] = *(const f32x2 *)&Qw[(size_t)(750 + k) * 100 + 2 * jp];
        }
    }
    {
        const float *Eb = E + (size_t)b * TT * QS;
        for (int i = tid; i < TT * QS; i += 512) {
            float s = Eb[i];
            #pragma unroll
            for (int p = 1; p < KSPLIT_E; p++) s += Eb[p * PSTRIDE + i];
            sE[i] = s;
        }
    }
    for (int i = tid; i < HSZ; i += 512) sH[i] = 0.f;
    __syncthreads();

    float *Hb = Hall + (size_t)b * TT * HSZ;

    #pragma unroll 1
    for (int t = 0; t < TT; t++) {
        if (act) {
            const float4 *sH4 = (const float4 *)&sH[ks * 40];
            f32x2 a0 = 0ull, a1 = 0ull;
            #pragma unroll
            for (int q = 0; q < 10; q++) {
                float4 h = sH4[q];
                fma2(a0, pk2(h.x, h.x), w1r[4 * q + 0]);
                fma2(a1, pk2(h.y, h.y), w1r[4 * q + 1]);
                fma2(a0, pk2(h.z, h.z), w1r[4 * q + 2]);
                fma2(a1, pk2(h.w, h.w), w1r[4 * q + 3]);
            }
            *(f32x2 *)&part[ks * 100 + 2 * jp] = add2(a0, a1);
        }
        __syncthreads();
        if (tid < 100) {
            float s = Rb[tid];
            #pragma unroll
            for (int ss = 0; ss < 10; ss++) s += part[ss * 100 + tid];
            sRt[tid] = tanhf(s);
        }
        __syncthreads();
        if (act) {
            f32x2 a = 0ull;
            #pragma unroll
            for (int kk = 0; kk < 10; kk++) {
                float h = sRt[ks * 10 + kk];
                fma2(a, pk2(h, h), w2r[kk]);
            }
            *(f32x2 *)&part[ks * 100 + 2 * jp] = a;
        }
        __syncthreads();
        if (tid < HSZ) {
            int j = tid % 100;
            float s = sE[t * QS + j];
            #pragma unroll
            for (int ss = 0; ss < 10; ss++) s += part[ss * 100 + j];
            float q = tanhf(s);
            const float alphas[4] = {0.0f, 0.25f, 0.5f, 0.95f};
            float al = alphas[tid / 100];
            float hn = al * sH[tid] + (1.f - al) * q;
            sH[tid] = hn;
            Hb[t * HSZ + tid] = hn;
        }
        __syncthreads();
    }
}

// =====================================================================
// Logits partials: grid (BB, 2) over i-halves; tanh(sum of O partials).
// Deterministic: each CTA writes its own partial row.
// =====================================================================
__global__ void __launch_bounds__(256) logits_kernel(
    const float *__restrict__ O, const float *__restrict__ OutW,
    float *__restrict__ lgpart)
{
    const int b = blockIdx.x, half = blockIdx.y, tid = threadIdx.x;
    const size_t base = (size_t)b * (TT * QS);
    const size_t PSTRIDE = (size_t)NIMG * QS;
    const int i0 = half * 3200, i1 = i0 + 3200;

    float acc[NCLS];
    #pragma unroll
    for (int c = 0; c < NCLS; c++) acc[c] = 0.f;

    for (int i = i0 + tid; i < i1; i += 256) {
        float s = 0.f;
        #pragma unroll
        for (int p = 0; p < KSPLIT_O; p++) s += O[p * PSTRIDE + base + i];
        float v = tanhf(s);
        const float *wr = OutW + (size_t)i * NCLS;
        #pragma unroll
        for (int c = 0; c < NCLS; c++) acc[c] += v * wr[c];
    }
    #pragma unroll
    for (int c = 0; c < NCLS; c++)
        #pragma unroll
        for (int o = 16; o > 0; o >>= 1)
            acc[c] += __shfl_down_sync(0xffffffffu, acc[c], o);

    __shared__ float wpart[8][NCLS];
    int w = tid >> 5, l = tid & 31;
    if (l == 0)
        #pragma unroll
        for (int c = 0; c < NCLS; c++) wpart[w][c] = acc[c];
    __syncthreads();

    if (tid < NCLS) {
        float s = 0.f;
        #pragma unroll
        for (int ww = 0; ww < 8; ww++) s += wpart[ww][tid];
        lgpart[(size_t)(half * BB + b) * NCLS + tid] = s;
    }
}

// =====================================================================
// Softmax: combine 2 logits partials + OutB; softmax over 10 classes.
// =====================================================================
__global__ void __launch_bounds__(32) softmax_kernel(
    const float *__restrict__ lgpart, const float *__restrict__ OutB,
    float *__restrict__ out)
{
    const int b = blockIdx.x, lane = threadIdx.x;
    __shared__ float sl[NCLS];
    __shared__ float smax, ssum;
    if (lane < NCLS) {
        sl[lane] = OutB[lane]
                 + lgpart[(size_t)b * NCLS + lane]
                 + lgpart[(size_t)(BB + b) * NCLS + lane];
    }
    __syncwarp();
    if (lane == 0) {
        float m = sl[0];
        #pragma unroll
        for (int c = 1; c < NCLS; c++) m = fmaxf(m, sl[c]);
        float su = 0.f;
        #pragma unroll
        for (int c = 0; c < NCLS; c++) su += expf(sl[c] - m);
        smax = m; ssum = su;
    }
    __syncwarp();
    if (lane < NCLS)
        out[(size_t)b * NCLS + lane] = expf(sl[lane] - smax) / ssum;
}

// =====================================================================
extern "C" void kernel_launch(void *const *d_in, const int *in_sizes, int n_in,
                              void *d_out, int out_size)
{
    const float *In     = (const float *)d_in[0];
    const float *conv1w = (const float *)d_in[1];
    const float *conv1b = (const float *)d_in[2];
    const float *conv2w = (const float *)d_in[3];
    const float *conv2b = (const float *)d_in[4];
    const float *Rw     = (const float *)d_in[5];
    const float *Rb     = (const float *)d_in[6];
    const float *Qw     = (const float *)d_in[7];
    const float *Qb     = (const float *)d_in[8];
    const float *Ow     = (const float *)d_in[9];
    const float *Obias  = (const float *)d_in[10];
    const float *OutW   = (const float *)d_in[11];
    const float *OutB   = (const float *)d_in[12];
    float *out = (float *)d_out;

    float *emb, *E, *Hall, *OutAll, *lgpart;
    cudaGetSymbolAddress((void **)&emb,    g_emb);
    cudaGetSymbolAddress((void **)&E,      g_E);
    cudaGetSymbolAddress((void **)&Hall,   g_Hall);
    cudaGetSymbolAddress((void **)&OutAll, g_OutAll);
    cudaGetSymbolAddress((void **)&lgpart, g_lgpart);

    cudaFuncSetAttribute(conv_embed_kernel,
                         cudaFuncAttributeMaxDynamicSharedMemorySize, CONV_SMEM);

    // 2 nops: ncu capture (4th launch) lands on the E-GEMM
    nop_kernel_a<<<1, 32>>>();
    nop_kernel_b<<<1, 32>>>();

    conv_embed_kernel<<<NIMG / 2, 256, CONV_SMEM>>>(In, conv1w, conv1b, conv2w, conv2b, emb);

    // E partials: K = 750, 3 splits, chunk 250 -> grid 384
    gemm100_ks_kernel<<<dim3(NIMG / 64, KSPLIT_E), 256>>>(emb, Qw, Qb, E, NIMG, EMB, 250);

    recurrence_kernel<<<BB, 512>>>(Rw, Rb, Qw, E, Hall);

    // O partials: K = 400, 2 splits, chunk 224
    gemm100_ks_kernel<<<dim3(NIMG / 64, KSPLIT_O), 256>>>(Hall, Ow, Obias, OutAll, NIMG, HSZ, 224);

    // logits split over 2 i-halves, then softmax combine
    logits_kernel<<<dim3(BB, 2), 256>>>(OutAll, OutW, lgpart);
    softmax_kernel<<<BB, 32>>>(lgpart, OutB, out);
}